// round 10
// baseline (speedup 1.0000x reference)
#include <cuda_runtime.h>
#include <cuda_fp16.h>
#include <cstdint>

#define HH 64
#define WW 64
#define CIN 256
#define XP 76
#define OC2 49
#define KTOT 12544              // 49 taps * 256 ic
#define NQ 49                   // chunks per CTA: 1 tap x 64 ic (this CTA's quarter)
#define SLAB_BYTES (152 * 128)  // 2 padded rows x 76 cols x 64 ic fp16, SW128
#define BTILE_BYTES (64 * 128)  // 64 oc x 64 ic fp16, SW128
#define BRING_OFF (2 * SLAB_BYTES)
#define SMEM_CONV (BRING_OFF + 2 * BTILE_BYTES)   // 55296 -> 3 CTAs/SM
#define GSTRIDE 28
#define SMEM_FW (25088 + 128 * 130 * 4)

// Scratch (device globals: zero-initialized, allocation-free, graph-capturable)
__device__ float  g_xpad[4 * CIN * XP * XP];     // NCHW padded fp32 (gather)
__device__ __half g_xn[4 * XP * XP * CIN];       // NHWC padded fp16 (conv A)
__device__ __half g_w12t[64 * KTOT];             // fused W^T [oc64][tap*256+ic] fp16
__device__ float  g_b12[OC2];                    // fused bias
__device__ float  g_k2[4 * 4 * OC2 * HH * WW];   // partial logits [icq][b][oc][px]
__device__ float  g_attn[4 * OC2 * HH * WW];     // softmax attention

// ---------------- helpers ----------------
__device__ __forceinline__ uint32_t smem_u32(const void* p) {
    uint32_t a;
    asm("{ .reg .u64 t; cvta.to.shared.u64 t, %1; cvt.u32.u64 %0, t; }" : "=r"(a) : "l"(p));
    return a;
}
__device__ __forceinline__ void cp16(uint32_t d, const void* s) {
    asm volatile("cp.async.cg.shared.global [%0], [%1], 16;" :: "r"(d), "l"(s));
}
__device__ __forceinline__ void cp4(uint32_t d, const void* s) {
    asm volatile("cp.async.ca.shared.global [%0], [%1], 4;" :: "r"(d), "l"(s));
}
#define CP_COMMIT() asm volatile("cp.async.commit_group;")
#define CP_WAIT(n)  asm volatile("cp.async.wait_group %0;" :: "n"(n))

__device__ __forceinline__ void mma_f16(float* c, uint32_t a0, uint32_t a1,
                                        uint32_t a2, uint32_t a3,
                                        uint32_t b0, uint32_t b1) {
    asm volatile(
        "mma.sync.aligned.m16n8k16.row.col.f32.f16.f16.f32 "
        "{%0,%1,%2,%3},{%4,%5,%6,%7},{%8,%9},{%0,%1,%2,%3};"
        : "+f"(c[0]), "+f"(c[1]), "+f"(c[2]), "+f"(c[3])
        : "r"(a0), "r"(a1), "r"(a2), "r"(a3), "r"(b0), "r"(b1));
}
__device__ __forceinline__ void ldm4(uint32_t* r, uint32_t addr) {
    asm volatile("ldmatrix.sync.aligned.m8n8.x4.shared.b16 {%0,%1,%2,%3}, [%4];"
        : "=r"(r[0]), "=r"(r[1]), "=r"(r[2]), "=r"(r[3]) : "r"(addr));
}

// ---------------------------------------------------------------------------
// Combined prep: x -> g_xpad (NCHW fp32) and g_xn (NHWC fp16), interiors only
// ---------------------------------------------------------------------------
__global__ __launch_bounds__(256) void prep_x(const float* __restrict__ x) {
    const int h = blockIdx.x, b = blockIdx.y;
    __half* outr = g_xn + (((size_t)b * XP + (h + 6))) * XP * CIN;
    __shared__ float sm[128 * 65];
    for (int half_i = 0; half_i < 2; half_i++) {
        const int ich = half_i * 128;
        for (int idx = threadIdx.x; idx < 128 * 64; idx += 256) {
            int icl = idx >> 6, w = idx & 63;
            sm[icl * 65 + w] = x[(((size_t)(b * CIN + ich + icl)) * HH + h) * WW + w];
        }
        __syncthreads();
        for (int idx = threadIdx.x; idx < 64 * 128; idx += 256) {
            int w = idx >> 7, icl = idx & 127;
            outr[(size_t)(w + 6) * CIN + ich + icl] = __float2half_rn(sm[icl * 65 + w]);
        }
        for (int idx = threadIdx.x; idx < 128 * 32; idx += 256) {
            int icl = idx >> 5, wp = (idx & 31) * 2;
            float2 v = make_float2(sm[icl * 65 + wp], sm[icl * 65 + wp + 1]);
            *(float2*)&g_xpad[((size_t)(b * CIN + ich + icl)) * XP * XP
                              + (h + 6) * XP + wp + 6] = v;
        }
        __syncthreads();
    }
}

// ---------------------------------------------------------------------------
// Fused weights as tiled GEMM over w1's native k' = ic*49+tap ordering.
// ---------------------------------------------------------------------------
__global__ __launch_bounds__(256) void fuse_w(const float* __restrict__ w1,
                                              const float* __restrict__ w2) {
    extern __shared__ float fsm[];
    float* w2s = fsm;
    float* sm  = fsm + OC2 * 128;
    const int tid = threadIdx.x;
    const int k0 = blockIdx.x * 128;

    for (int i = tid; i < OC2 * 128; i += 256) w2s[i] = w2[i];
    for (int i = tid; i < 128 * 128; i += 256) {
        int m = i >> 7, kcl = i & 127;
        sm[m * 130 + kcl] = w1[(size_t)m * KTOT + k0 + kcl];
    }
    __syncthreads();

    const int och = tid >> 6;
    const int kc0 = (tid & 63) * 2;
    const int oc0 = och * 12;
    const int ocn = (och < 3) ? 12 : 13;

    float accx[13], accy[13];
#pragma unroll
    for (int j = 0; j < 13; j++) { accx[j] = 0.f; accy[j] = 0.f; }

#pragma unroll 4
    for (int m = 0; m < 128; m++) {
        const float2 a = *(const float2*)&sm[m * 130 + kc0];
#pragma unroll
        for (int j = 0; j < 13; j++) {
            if (j < ocn) {
                const float wv = w2s[(oc0 + j) * 128 + m];
                accx[j] = fmaf(wv, a.x, accx[j]);
                accy[j] = fmaf(wv, a.y, accy[j]);
            }
        }
    }
#pragma unroll
    for (int j = 0; j < 13; j++) {
        if (j < ocn) {
#pragma unroll
            for (int e = 0; e < 2; e++) {
                const int kp = k0 + kc0 + e;
                const int ic = kp / 49, tap = kp - ic * 49;
                g_w12t[(size_t)(oc0 + j) * KTOT + tap * 256 + ic] =
                    __float2half_rn(e ? accy[j] : accx[j]);
            }
        }
    }
}

__global__ __launch_bounds__(128) void bias_fuse(const float* __restrict__ w2,
                                                 const float* __restrict__ b1,
                                                 const float* __restrict__ b2) {
    const int oc = blockIdx.x, tid = threadIdx.x;
    float v = w2[oc * 128 + tid] * b1[tid];
#pragma unroll
    for (int off = 16; off > 0; off >>= 1)
        v += __shfl_xor_sync(0xFFFFFFFFu, v, off);
    __shared__ float ws[4];
    if ((tid & 31) == 0) ws[tid >> 5] = v;
    __syncthreads();
    if (tid == 0) g_b12[oc] = ws[0] + ws[1] + ws[2] + ws[3] + b2[oc];
}

// ---------------------------------------------------------------------------
// fp16 mma.sync implicit-GEMM conv, K split across 4 CTAs (64-ic quarters).
// CTA: M=128 px, N=64 oc, K=3136 in 49 chunks (1 tap x 64 ic).
// SW128 smem (128B rows), 55 KB/CTA -> 3 CTAs/SM. Partial logits to g_k2.
// ---------------------------------------------------------------------------
__global__ __launch_bounds__(256) void conv_mma() {
    extern __shared__ __align__(16) char smem[];
    const uint32_t sbase = smem_u32(smem);
    const int tid = threadIdx.x, wid = tid >> 5, lane = tid & 31;
    const int gid = lane >> 2, tg = lane & 3;
    const int hr0 = blockIdx.x * 2, b = blockIdx.y, icq = blockIdx.z;
    const int mbase = (wid >> 1) * 32, nbase = (wid & 1) * 32;
    const int icbase = icq * 64;

    float acc[2][4][4];
#pragma unroll
    for (int mt = 0; mt < 2; mt++)
#pragma unroll
        for (int nt = 0; nt < 4; nt++)
#pragma unroll
            for (int r = 0; r < 4; r++) acc[mt][nt][r] = 0.f;

    const int lhi16 = lane >> 4;            // 0/1 : A k-unit select
    const int bhi = (lane >> 3) & 1;        // 0/1 : B k-unit select
    int arow0[2];
    {
        const int rsel = ((lane >> 3) & 1) * 8 + (lane & 7);
#pragma unroll
        for (int mt = 0; mt < 2; mt++)
            arow0[mt] = (mbase >> 6) * 76 + (mbase & 63) + mt * 16 + rsel;
    }
    int brow[2];
#pragma unroll
    for (int ntp = 0; ntp < 2; ntp++)
        brow[ntp] = nbase + ntp * 16 + (lane >> 4) * 8 + (lane & 7);

    const __half* xb = g_xn + (size_t)b * XP * XP * CIN;

// slab u: 2 padded rows (hr0+2u, +1) x 76 cols x this CTA's 64 ic
#define COPY_SLAB(u, slot) do {                                                 \
    const __half* _src = xb + ((size_t)(hr0 + 2 * (u)) * XP) * CIN + icbase;    \
    const uint32_t _dst = sbase + (slot) * SLAB_BYTES;                          \
    for (int _i = tid; _i < 1216; _i += 256) {                                  \
        int _row = _i >> 3, _j = _i & 7;                                        \
        int _pr = _row / 76, _col = _row - _pr * 76;                            \
        cp16(_dst + _row * 128 + ((_j ^ (_row & 7)) << 4),                      \
             _src + ((size_t)_pr * XP + _col) * CIN + _j * 8);                  \
    }                                                                           \
} while (0)

// chunk q == tap q
#define COPY_B(q, slot) do {                                                    \
    const __half* _bs = g_w12t + (q) * 256 + icbase;                            \
    const uint32_t _dst = sbase + BRING_OFF + (slot) * BTILE_BYTES;             \
    for (int _i = tid; _i < 512; _i += 256) {                                   \
        int _oc = _i >> 3, _j = _i & 7;                                         \
        cp16(_dst + _oc * 128 + ((_j ^ (_oc & 7)) << 4),                        \
             _bs + (size_t)_oc * KTOT + _j * 8);                                \
    }                                                                           \
} while (0)

    COPY_SLAB(0, 0); COPY_B(0, 0); CP_COMMIT();

#pragma unroll 1
    for (int q = 0; q < NQ; q++) {
        CP_WAIT(0);
        __syncthreads();
        const int s = q / 7, v = q - s * 7;
        if (v == 0 && s + 1 < 7) COPY_SLAB(s + 1, (s + 1) & 1);
        if (q + 1 < NQ) COPY_B(q + 1, (q + 1) & 1);
        CP_COMMIT();

        const uint32_t Aaddr = sbase + (s & 1) * SLAB_BYTES;
        const uint32_t Baddr = sbase + BRING_OFF + (q & 1) * BTILE_BYTES;
        uint32_t Abase[2], Bbase[2];
        int amask[2], bmask[2];
#pragma unroll
        for (int mt = 0; mt < 2; mt++) {
            const int r = arow0[mt] + 2 * v;
            Abase[mt] = Aaddr + r * 128;
            amask[mt] = r & 7;
        }
#pragma unroll
        for (int ntp = 0; ntp < 2; ntp++) {
            Bbase[ntp] = Baddr + brow[ntp] * 128;
            bmask[ntp] = brow[ntp] & 7;
        }
#pragma unroll
        for (int ks = 0; ks < 4; ks++) {
            uint32_t Ar[2][4], Br[2][4];
            ldm4(Ar[0], Abase[0] + (((2 * ks + lhi16) ^ amask[0]) << 4));
            ldm4(Ar[1], Abase[1] + (((2 * ks + lhi16) ^ amask[1]) << 4));
            ldm4(Br[0], Bbase[0] + (((2 * ks + bhi) ^ bmask[0]) << 4));
            ldm4(Br[1], Bbase[1] + (((2 * ks + bhi) ^ bmask[1]) << 4));
#pragma unroll
            for (int mt = 0; mt < 2; mt++)
#pragma unroll
                for (int nt = 0; nt < 4; nt++)
                    mma_f16(acc[mt][nt], Ar[mt][0], Ar[mt][1], Ar[mt][2], Ar[mt][3],
                            Br[nt >> 1][(nt & 1) * 2], Br[nt >> 1][(nt & 1) * 2 + 1]);
        }
    }

    // ---------------- epilogue: partial logits -> g_k2 (coalesced) ----------
    __syncthreads();
    float* lg = (float*)smem;               // [128][66]
#pragma unroll
    for (int mt = 0; mt < 2; mt++) {
        const int row0 = mbase + mt * 16 + gid;
#pragma unroll
        for (int nt = 0; nt < 4; nt++) {
            const int col = nbase + nt * 8 + tg * 2;
            *(float2*)&lg[row0 * 66 + col] =
                make_float2(acc[mt][nt][0], acc[mt][nt][1]);
            *(float2*)&lg[(row0 + 8) * 66 + col] =
                make_float2(acc[mt][nt][2], acc[mt][nt][3]);
        }
    }
    __syncthreads();
    if (tid < 128) {
        const float* p = lg + tid * 66;
        float* dst = g_k2 + ((size_t)(icq * 4 + b) * OC2) * (HH * WW)
                     + (hr0 + (tid >> 6)) * WW + (tid & 63);
#pragma unroll
        for (int k = 0; k < OC2; k++)
            dst[(size_t)k * (HH * WW)] = p[k];
    }
#undef COPY_SLAB
#undef COPY_B
}

// ---------------------------------------------------------------------------
// Sum 4 ic-partials + fused bias, softmax over 49 channels -> g_attn
// ---------------------------------------------------------------------------
__global__ __launch_bounds__(128) void softmax_k() {
    const int b = blockIdx.y;
    const int px = blockIdx.x * 128 + threadIdx.x;
    __shared__ float bs[OC2];
    if (threadIdx.x < OC2) bs[threadIdx.x] = g_b12[threadIdx.x];
    __syncthreads();

    float v[OC2];
    float mx = -1e30f;
#pragma unroll
    for (int k = 0; k < OC2; k++) {
        float t = bs[k];
#pragma unroll
        for (int icq = 0; icq < 4; icq++)
            t += g_k2[((size_t)(icq * 4 + b) * OC2 + k) * (HH * WW) + px];
        v[k] = t;
        mx = fmaxf(mx, t);
    }
    float s = 0.f;
#pragma unroll
    for (int k = 0; k < OC2; k++) { v[k] = __expf(v[k] - mx); s += v[k]; }
    const float inv = 1.f / s;
#pragma unroll
    for (int k = 0; k < OC2; k++)
        g_attn[((size_t)(b * OC2 + k)) * (HH * WW) + px] = v[k] * inv;
}

// ---------------------------------------------------------------------------
// Gather: out[b,c,h,w] = sum_k attn[b,k,h,w] * xpad[b,c,h+2u,w+2v]
// 4 channels interleaved in smem (float4 per spatial site); cp.async 4B fills.
// ---------------------------------------------------------------------------
__global__ __launch_bounds__(256) void gather_kernel(float* __restrict__ out) {
    const int tile = blockIdx.x;                 // 8 h-tiles x 4 w-tiles
    const int h0 = (tile >> 2) * 8, w0 = (tile & 3) * 16;
    const int b = blockIdx.z;
    const int tid = threadIdx.x;
    const int sub = tid >> 7, stid = tid & 127;
    const int rr = stid >> 4, cc = stid & 15;
    const int h = h0 + rr, w = w0 + cc;
    const int c0 = blockIdx.y * 128 + sub * 64;

    // [buf][sub][site*4 + ch] : 20x28 sites x 4 interleaved channels
    __shared__ __align__(16) float xsm[3][2][20 * GSTRIDE * 4];

    float attn[OC2];
#pragma unroll
    for (int k = 0; k < OC2; k++)
        attn[k] = g_attn[(((size_t)(b * OC2 + k)) * HH + h) * WW + w];

    uint32_t sb[3];
#pragma unroll
    for (int s = 0; s < 3; s++) sb[s] = smem_u32(&xsm[s][sub][0]);

    const float* plane0 = g_xpad + (((size_t)(b * CIN + c0)) * XP + h0) * XP + w0;

#define CPG(g, st) do {                                                         \
    for (int _ch = 0; _ch < 4; _ch++) {                                         \
        const float* _src = plane0 + (size_t)(4 * (g) + _ch) * XP * XP;         \
        const uint32_t _d = sb[st] + _ch * 4;                                   \
        for (int _i = stid; _i < 560; _i += 128) {                              \
            int _r = _i / GSTRIDE, _c = _i - _r * GSTRIDE;                      \
            cp4(_d + _i * 16, _src + _r * XP + _c);                             \
        }                                                                       \
    }                                                                           \
} while (0)

    CPG(0, 0); CP_COMMIT();
    CPG(1, 1); CP_COMMIT();

#pragma unroll 1
    for (int g = 0; g < 16; g++) {
        CP_WAIT(1);
        __syncthreads();
        if (g + 2 < 16) { CPG(g + 2, (g + 2) % 3); }
        CP_COMMIT();

        const float* xs = &xsm[g % 3][sub][0];
        float4 o = make_float4(0.f, 0.f, 0.f, 0.f);
#pragma unroll
        for (int u = 0; u < 7; u++)
#pragma unroll
            for (int v = 0; v < 7; v++) {
                const float4 xv = *(const float4*)&xs[((rr + 2 * u) * GSTRIDE
                                                       + cc + 2 * v) * 4];
                const float a = attn[u * 7 + v];
                o.x = fmaf(a, xv.x, o.x);
                o.y = fmaf(a, xv.y, o.y);
                o.z = fmaf(a, xv.z, o.z);
                o.w = fmaf(a, xv.w, o.w);
            }
        float* dst = out + (((size_t)(b * CIN + c0 + 4 * g)) * HH + h) * WW + w;
        dst[0] = o.x;
        dst[HH * WW] = o.y;
        dst[2 * HH * WW] = o.z;
        dst[3 * HH * WW] = o.w;
    }
#undef CPG
}

// ---------------------------------------------------------------------------
extern "C" void kernel_launch(void* const* d_in, const int* in_sizes, int n_in,
                              void* d_out, int out_size)
{
    const float* x  = (const float*)d_in[0];
    const float* w1 = (const float*)d_in[1];
    const float* b1 = (const float*)d_in[2];
    const float* w2 = (const float*)d_in[3];
    const float* b2 = (const float*)d_in[4];
    float* out = (float*)d_out;

    cudaFuncSetAttribute(conv_mma, cudaFuncAttributeMaxDynamicSharedMemorySize,
                         SMEM_CONV);
    cudaFuncSetAttribute(fuse_w, cudaFuncAttributeMaxDynamicSharedMemorySize,
                         SMEM_FW);

    prep_x<<<dim3(HH, 4), 256>>>(x);
    fuse_w<<<98, 256, SMEM_FW>>>(w1, w2);
    bias_fuse<<<49, 128>>>(w2, b1, b2);
    conv_mma<<<dim3(32, 4, 4), 256, SMEM_CONV>>>();
    softmax_k<<<dim3(32, 4), 128>>>();
    gather_kernel<<<dim3(32, 2, 4), 256>>>(out);
}

// round 11
// speedup vs baseline: 1.0950x; 1.0950x over previous
#include <cuda_runtime.h>
#include <cuda_fp16.h>
#include <cstdint>

#define HH 64
#define WW 64
#define CIN 256
#define XP 76
#define OC2 49
#define KTOT 12544              // 49 taps * 256 ic
#define NQ 49                   // chunks per CTA: 1 tap x 128 ic (this CTA's half)
#define SLAB_BYTES (152 * 256)  // 2 padded rows x 76 cols x 128 ic fp16, swizzled
#define BTILE_BYTES (64 * 256)  // 64 oc x 128 ic fp16, swizzled
#define BRING_OFF (2 * SLAB_BYTES)
#define SMEM_CONV (BRING_OFF + 2 * BTILE_BYTES)   // 110592 -> 2 CTAs/SM
#define GSTRIDE 48
#define SMEM_FW (25088 + 128 * 130 * 4)

// Scratch (device globals: zero-initialized, allocation-free, graph-capturable)
__device__ float  g_xpad[4 * CIN * XP * XP];     // NCHW padded fp32 (gather)
__device__ __half g_xn[4 * XP * XP * CIN];       // NHWC padded fp16 (conv A)
__device__ __half g_w12t[64 * KTOT];             // fused W^T [oc64][tap*256+ic] fp16
__device__ float  g_b12[OC2];                    // fused bias
__device__ float  g_k2[2 * 4 * OC2 * HH * WW];   // partial logits [icq][b][oc][px]
__device__ float  g_attn[4 * OC2 * HH * WW];     // softmax attention
__device__ int    g_cnt[128];                    // completion counters [b*32+tile]

// ---------------- helpers ----------------
__device__ __forceinline__ uint32_t smem_u32(const void* p) {
    uint32_t a;
    asm("{ .reg .u64 t; cvta.to.shared.u64 t, %1; cvt.u32.u64 %0, t; }" : "=r"(a) : "l"(p));
    return a;
}
__device__ __forceinline__ void cp16(uint32_t d, const void* s) {
    asm volatile("cp.async.cg.shared.global [%0], [%1], 16;" :: "r"(d), "l"(s));
}
#define CP_COMMIT() asm volatile("cp.async.commit_group;")
#define CP_WAIT(n)  asm volatile("cp.async.wait_group %0;" :: "n"(n))

__device__ __forceinline__ void mma_f16(float* c, uint32_t a0, uint32_t a1,
                                        uint32_t a2, uint32_t a3,
                                        uint32_t b0, uint32_t b1) {
    asm volatile(
        "mma.sync.aligned.m16n8k16.row.col.f32.f16.f16.f32 "
        "{%0,%1,%2,%3},{%4,%5,%6,%7},{%8,%9},{%0,%1,%2,%3};"
        : "+f"(c[0]), "+f"(c[1]), "+f"(c[2]), "+f"(c[3])
        : "r"(a0), "r"(a1), "r"(a2), "r"(a3), "r"(b0), "r"(b1));
}
__device__ __forceinline__ void ldm4(uint32_t* r, uint32_t addr) {
    asm volatile("ldmatrix.sync.aligned.m8n8.x4.shared.b16 {%0,%1,%2,%3}, [%4];"
        : "=r"(r[0]), "=r"(r[1]), "=r"(r[2]), "=r"(r[3]) : "r"(addr));
}

// ---------------------------------------------------------------------------
// Combined prep: x -> g_xpad (NCHW fp32) and g_xn (NHWC fp16), interiors only
// ---------------------------------------------------------------------------
__global__ __launch_bounds__(256) void prep_x(const float* __restrict__ x) {
    const int h = blockIdx.x, b = blockIdx.y;
    __half* outr = g_xn + (((size_t)b * XP + (h + 6))) * XP * CIN;
    __shared__ float sm[128 * 65];
    for (int half_i = 0; half_i < 2; half_i++) {
        const int ich = half_i * 128;
        for (int idx = threadIdx.x; idx < 128 * 64; idx += 256) {
            int icl = idx >> 6, w = idx & 63;
            sm[icl * 65 + w] = x[(((size_t)(b * CIN + ich + icl)) * HH + h) * WW + w];
        }
        __syncthreads();
        for (int idx = threadIdx.x; idx < 64 * 128; idx += 256) {
            int w = idx >> 7, icl = idx & 127;
            outr[(size_t)(w + 6) * CIN + ich + icl] = __float2half_rn(sm[icl * 65 + w]);
        }
        for (int idx = threadIdx.x; idx < 128 * 32; idx += 256) {
            int icl = idx >> 5, wp = (idx & 31) * 2;
            float2 v = make_float2(sm[icl * 65 + wp], sm[icl * 65 + wp + 1]);
            *(float2*)&g_xpad[((size_t)(b * CIN + ich + icl)) * XP * XP
                              + (h + 6) * XP + wp + 6] = v;
        }
        __syncthreads();
    }
}

// ---------------------------------------------------------------------------
// Fused weights as tiled GEMM over w1's native k' = ic*49+tap ordering.
// ---------------------------------------------------------------------------
__global__ __launch_bounds__(256) void fuse_w(const float* __restrict__ w1,
                                              const float* __restrict__ w2) {
    extern __shared__ float fsm[];
    float* w2s = fsm;
    float* sm  = fsm + OC2 * 128;
    const int tid = threadIdx.x;
    const int k0 = blockIdx.x * 128;

    for (int i = tid; i < OC2 * 128; i += 256) w2s[i] = w2[i];
    for (int i = tid; i < 128 * 128; i += 256) {
        int m = i >> 7, kcl = i & 127;
        sm[m * 130 + kcl] = w1[(size_t)m * KTOT + k0 + kcl];
    }
    __syncthreads();

    const int och = tid >> 6;
    const int kc0 = (tid & 63) * 2;
    const int oc0 = och * 12;
    const int ocn = (och < 3) ? 12 : 13;

    float accx[13], accy[13];
#pragma unroll
    for (int j = 0; j < 13; j++) { accx[j] = 0.f; accy[j] = 0.f; }

#pragma unroll 4
    for (int m = 0; m < 128; m++) {
        const float2 a = *(const float2*)&sm[m * 130 + kc0];
#pragma unroll
        for (int j = 0; j < 13; j++) {
            if (j < ocn) {
                const float wv = w2s[(oc0 + j) * 128 + m];
                accx[j] = fmaf(wv, a.x, accx[j]);
                accy[j] = fmaf(wv, a.y, accy[j]);
            }
        }
    }
#pragma unroll
    for (int j = 0; j < 13; j++) {
        if (j < ocn) {
#pragma unroll
            for (int e = 0; e < 2; e++) {
                const int kp = k0 + kc0 + e;
                const int ic = kp / 49, tap = kp - ic * 49;
                g_w12t[(size_t)(oc0 + j) * KTOT + tap * 256 + ic] =
                    __float2half_rn(e ? accy[j] : accx[j]);
            }
        }
    }
}

__global__ __launch_bounds__(128) void bias_fuse(const float* __restrict__ w2,
                                                 const float* __restrict__ b1,
                                                 const float* __restrict__ b2) {
    const int oc = blockIdx.x, tid = threadIdx.x;
    float v = w2[oc * 128 + tid] * b1[tid];
#pragma unroll
    for (int off = 16; off > 0; off >>= 1)
        v += __shfl_xor_sync(0xFFFFFFFFu, v, off);
    __shared__ float ws[4];
    if ((tid & 31) == 0) ws[tid >> 5] = v;
    __syncthreads();
    if (tid == 0) g_b12[oc] = ws[0] + ws[1] + ws[2] + ws[3] + b2[oc];
}

// ---------------------------------------------------------------------------
// fp16 mma.sync implicit-GEMM conv, K split across 2 CTAs (ic halves),
// fragment-double-buffered ks loop, softmax fused into the last-finishing CTA.
// ---------------------------------------------------------------------------
__global__ __launch_bounds__(256) void conv_mma() {
    extern __shared__ __align__(16) char smem[];
    const uint32_t sbase = smem_u32(smem);
    const int tid = threadIdx.x, wid = tid >> 5, lane = tid & 31;
    const int gid = lane >> 2, tg = lane & 3;
    const int hr0 = blockIdx.x * 2, b = blockIdx.y, icq = blockIdx.z;
    const int mbase = (wid >> 1) * 32, nbase = (wid & 1) * 32;
    const int icbase = icq * 128;

    float acc[2][4][4];
#pragma unroll
    for (int mt = 0; mt < 2; mt++)
#pragma unroll
        for (int nt = 0; nt < 4; nt++)
#pragma unroll
            for (int r = 0; r < 4; r++) acc[mt][nt][r] = 0.f;

    const int lhi16 = lane >> 4;
    const int bhi = (lane >> 3) & 1;
    int arow0[2];
    {
        const int rsel = ((lane >> 3) & 1) * 8 + (lane & 7);
#pragma unroll
        for (int mt = 0; mt < 2; mt++)
            arow0[mt] = (mbase >> 6) * 76 + (mbase & 63) + mt * 16 + rsel;
    }
    int brow[2];
#pragma unroll
    for (int ntp = 0; ntp < 2; ntp++)
        brow[ntp] = nbase + ntp * 16 + (lane >> 4) * 8 + (lane & 7);

    const __half* xb = g_xn + (size_t)b * XP * XP * CIN;

#define COPY_SLAB(u, slot) do {                                                 \
    const __half* _src = xb + ((size_t)(hr0 + 2 * (u)) * XP) * CIN + icbase;    \
    const uint32_t _dst = sbase + (slot) * SLAB_BYTES;                          \
    for (int _i = tid; _i < 2432; _i += 256) {                                  \
        int _row = _i >> 4, _j = _i & 15;                                       \
        int _pr = _row / 76, _col = _row - _pr * 76;                            \
        cp16(_dst + _row * 256 + ((_j ^ (_row & 7)) << 4),                      \
             _src + ((size_t)_pr * XP + _col) * CIN + _j * 8);                  \
    }                                                                           \
} while (0)

#define COPY_B(q, slot) do {                                                    \
    const __half* _bs = g_w12t + (q) * 256 + icbase;                            \
    const uint32_t _dst = sbase + BRING_OFF + (slot) * BTILE_BYTES;             \
    for (int _i = tid; _i < 1024; _i += 256) {                                  \
        int _oc = _i >> 4, _j = _i & 15;                                        \
        cp16(_dst + _oc * 256 + ((_j ^ (_oc & 7)) << 4),                        \
             _bs + (size_t)_oc * KTOT + _j * 8);                                \
    }                                                                           \
} while (0)

#define LOAD_FRAG(ks, buf) do {                                                 \
    ldm4(Ar[buf][0], Abase[0] + (((2 * (ks) + lhi16) ^ amask[0]) << 4));        \
    ldm4(Ar[buf][1], Abase[1] + (((2 * (ks) + lhi16) ^ amask[1]) << 4));        \
    ldm4(Br[buf][0], Bbase[0] + (((2 * (ks) + bhi) ^ bmask[0]) << 4));          \
    ldm4(Br[buf][1], Bbase[1] + (((2 * (ks) + bhi) ^ bmask[1]) << 4));          \
} while (0)

    COPY_SLAB(0, 0); COPY_B(0, 0); CP_COMMIT();

#pragma unroll 1
    for (int q = 0; q < NQ; q++) {
        CP_WAIT(0);
        __syncthreads();
        const int s = q / 7, v = q - s * 7;
        if (v == 0 && s + 1 < 7) COPY_SLAB(s + 1, (s + 1) & 1);
        if (q + 1 < NQ) COPY_B(q + 1, (q + 1) & 1);
        CP_COMMIT();

        const uint32_t Aaddr = sbase + (s & 1) * SLAB_BYTES;
        const uint32_t Baddr = sbase + BRING_OFF + (q & 1) * BTILE_BYTES;
        uint32_t Abase[2], Bbase[2];
        int amask[2], bmask[2];
#pragma unroll
        for (int mt = 0; mt < 2; mt++) {
            const int r = arow0[mt] + 2 * v;
            Abase[mt] = Aaddr + r * 256;
            amask[mt] = r & 7;
        }
#pragma unroll
        for (int ntp = 0; ntp < 2; ntp++) {
            Bbase[ntp] = Baddr + brow[ntp] * 256;
            bmask[ntp] = brow[ntp] & 7;
        }

        uint32_t Ar[2][2][4], Br[2][2][4];      // [buf][frag][reg]
        LOAD_FRAG(0, 0);
#pragma unroll
        for (int ks = 0; ks < 8; ks++) {
            const int cur = ks & 1;
            if (ks < 7) { LOAD_FRAG(ks + 1, cur ^ 1); }
#pragma unroll
            for (int mt = 0; mt < 2; mt++)
#pragma unroll
                for (int nt = 0; nt < 4; nt++)
                    mma_f16(acc[mt][nt],
                            Ar[cur][mt][0], Ar[cur][mt][1],
                            Ar[cur][mt][2], Ar[cur][mt][3],
                            Br[cur][nt >> 1][(nt & 1) * 2],
                            Br[cur][nt >> 1][(nt & 1) * 2 + 1]);
        }
    }

    // ---- epilogue: logits -> smem, partial -> g_k2, last CTA does softmax ----
    __syncthreads();
    float* lg = (float*)smem;               // [128][66]
#pragma unroll
    for (int mt = 0; mt < 2; mt++) {
        const int row0 = mbase + mt * 16 + gid;
#pragma unroll
        for (int nt = 0; nt < 4; nt++) {
            const int col = nbase + nt * 8 + tg * 2;
            *(float2*)&lg[row0 * 66 + col] =
                make_float2(acc[mt][nt][0], acc[mt][nt][1]);
            *(float2*)&lg[(row0 + 8) * 66 + col] =
                make_float2(acc[mt][nt][2], acc[mt][nt][3]);
        }
    }
    __syncthreads();
    const int pxoff = (hr0 + (tid >> 6)) * WW + ((tid & 63));
    if (tid < 128) {
        const float* p = lg + tid * 66;
        float* dst = g_k2 + ((size_t)(icq * 4 + b) * OC2) * (HH * WW) + pxoff;
#pragma unroll
        for (int k = 0; k < OC2; k++)
            dst[(size_t)k * (HH * WW)] = p[k];
    }
    __threadfence();
    __syncthreads();
    __shared__ int lastf;
    if (tid == 0)
        lastf = atomicAdd(&g_cnt[blockIdx.y * 32 + blockIdx.x], 1);
    __syncthreads();
    if (lastf == 1) {
        __threadfence();
        if (tid < 128) {
            const float* p = lg + tid * 66;
            const float* qv = g_k2 + ((size_t)((1 - icq) * 4 + b) * OC2) * (HH * WW)
                              + pxoff;
            float e[OC2];
            float mx = -1e30f;
#pragma unroll
            for (int k = 0; k < OC2; k++) {
                e[k] = p[k] + qv[(size_t)k * (HH * WW)] + __ldg(&g_b12[k]);
                mx = fmaxf(mx, e[k]);
            }
            float sum = 0.f;
#pragma unroll
            for (int k = 0; k < OC2; k++) { e[k] = __expf(e[k] - mx); sum += e[k]; }
            const float inv = 1.f / sum;
            float* dst = g_attn + ((size_t)(b * OC2)) * (HH * WW) + pxoff;
#pragma unroll
            for (int k = 0; k < OC2; k++)
                dst[(size_t)k * (HH * WW)] = e[k] * inv;
        }
        __syncthreads();
        if (tid == 0) g_cnt[blockIdx.y * 32 + blockIdx.x] = 0;   // reset for replay
    }
#undef COPY_SLAB
#undef COPY_B
#undef LOAD_FRAG
}

// ---------------------------------------------------------------------------
// Gather: out[b,c,h,w] = sum_k attn[b,k,h,w] * xpad[b,c,h+2u,w+2v]
// 4 channels per group, separate buffers, cp16 fills, 3-buffer ring.
// ---------------------------------------------------------------------------
__global__ __launch_bounds__(256) void gather_kernel(float* __restrict__ out) {
    const int tile = blockIdx.x;                 // 8 h-tiles x 4 w-tiles
    const int h0 = (tile >> 2) * 8, w0 = (tile & 3) * 16;
    const int b = blockIdx.z;
    const int tid = threadIdx.x;
    const int sub = tid >> 7, stid = tid & 127;
    const int rr = stid >> 4, cc = stid & 15;
    const int h = h0 + rr, w = w0 + cc;
    const int c0 = blockIdx.y * 128 + sub * 64;

    __shared__ __align__(16) float xsm[3][2][4][20 * GSTRIDE];

    float attn[OC2];
#pragma unroll
    for (int k = 0; k < OC2; k++)
        attn[k] = g_attn[(((size_t)(b * OC2 + k)) * HH + h) * WW + w];

    uint32_t sb[3];
#pragma unroll
    for (int s = 0; s < 3; s++) sb[s] = smem_u32(&xsm[s][sub][0][0]);

    const float* plane0 = g_xpad + (((size_t)(b * CIN + c0)) * XP + h0) * XP + w0;

#define CPG(g, st) do {                                                         \
    for (int _ch = 0; _ch < 4; _ch++) {                                         \
        const float* _src = plane0 + (size_t)(4 * (g) + _ch) * XP * XP;         \
        const uint32_t _d = sb[st] + _ch * (20 * GSTRIDE * 4);                  \
        for (int _i = stid; _i < 140; _i += 128) {                              \
            int _r = _i / 7, _j = _i - _r * 7;                                  \
            cp16(_d + (_r * GSTRIDE + _j * 4) * 4, _src + _r * XP + _j * 4);    \
        }                                                                       \
    }                                                                           \
} while (0)

    CPG(0, 0); CP_COMMIT();
    CPG(1, 1); CP_COMMIT();

#pragma unroll 1
    for (int g = 0; g < 16; g++) {
        CP_WAIT(1);
        __syncthreads();
        if (g + 2 < 16) { CPG(g + 2, (g + 2) % 3); }
        CP_COMMIT();

        const float* xs = &xsm[g % 3][sub][0][0];
        float o0 = 0.f, o1 = 0.f, o2 = 0.f, o3 = 0.f;
#pragma unroll
        for (int u = 0; u < 7; u++)
#pragma unroll
            for (int v = 0; v < 7; v++) {
                const int idx = (rr + 2 * u) * GSTRIDE + cc + 2 * v;
                const float a = attn[u * 7 + v];
                o0 = fmaf(a, xs[idx], o0);
                o1 = fmaf(a, xs[idx + 960], o1);
                o2 = fmaf(a, xs[idx + 1920], o2);
                o3 = fmaf(a, xs[idx + 2880], o3);
            }
        float* dst = out + (((size_t)(b * CIN + c0 + 4 * g)) * HH + h) * WW + w;
        dst[0] = o0;
        dst[HH * WW] = o1;
        dst[2 * HH * WW] = o2;
        dst[3 * HH * WW] = o3;
    }
#undef CPG
}

// ---------------------------------------------------------------------------
extern "C" void kernel_launch(void* const* d_in, const int* in_sizes, int n_in,
                              void* d_out, int out_size)
{
    const float* x  = (const float*)d_in[0];
    const float* w1 = (const float*)d_in[1];
    const float* b1 = (const float*)d_in[2];
    const float* w2 = (const float*)d_in[3];
    const float* b2 = (const float*)d_in[4];
    float* out = (float*)d_out;

    cudaFuncSetAttribute(conv_mma, cudaFuncAttributeMaxDynamicSharedMemorySize,
                         SMEM_CONV);
    cudaFuncSetAttribute(fuse_w, cudaFuncAttributeMaxDynamicSharedMemorySize,
                         SMEM_FW);

    prep_x<<<dim3(HH, 4), 256>>>(x);
    fuse_w<<<98, 256, SMEM_FW>>>(w1, w2);
    bias_fuse<<<49, 128>>>(w2, b1, b2);
    conv_mma<<<dim3(32, 4, 2), 256, SMEM_CONV>>>();
    gather_kernel<<<dim3(32, 2, 4), 256>>>(out);
}

// round 12
// speedup vs baseline: 1.1512x; 1.0514x over previous
#include <cuda_runtime.h>
#include <cuda_fp16.h>
#include <cstdint>

#define HH 64
#define WW 64
#define CIN 256
#define XP 76
#define OC2 49
#define KTOT 12544              // 49 taps * 256 ic
#define NQ 49                   // chunks per CTA: 1 tap x 128 ic (this CTA's half)
#define SLAB_BYTES (152 * 256)  // 2 padded rows x 76 cols x 128 ic fp16, swizzled
#define BTILE_BYTES (64 * 256)  // 64 oc x 128 ic fp16, swizzled
#define BRING_OFF (2 * SLAB_BYTES)
#define SMEM_CONV (BRING_OFF + 2 * BTILE_BYTES)   // 110592 -> 2 CTAs/SM
#define GSTRIDE 48
#define SMEM_FW (25088 + 128 * 130 * 4)

// Scratch (device globals: zero-initialized, allocation-free, graph-capturable)
__device__ float  g_xpad[4 * CIN * XP * XP];     // NCHW padded fp32 (gather)
__device__ __half g_xn[4 * XP * XP * CIN];       // NHWC padded fp16 (conv A)
__device__ __half g_w12t[64 * KTOT];             // fused W^T [oc64][tap*256+ic] fp16
__device__ float  g_b12[OC2];                    // fused bias
__device__ float  g_k2[2 * 4 * OC2 * HH * WW];   // partial logits [icq][b][oc][px]
__device__ float  g_attn[4 * OC2 * HH * WW];     // softmax attention

// ---------------- helpers ----------------
__device__ __forceinline__ uint32_t smem_u32(const void* p) {
    uint32_t a;
    asm("{ .reg .u64 t; cvta.to.shared.u64 t, %1; cvt.u32.u64 %0, t; }" : "=r"(a) : "l"(p));
    return a;
}
__device__ __forceinline__ void cp16(uint32_t d, const void* s) {
    asm volatile("cp.async.cg.shared.global [%0], [%1], 16;" :: "r"(d), "l"(s));
}
#define CP_COMMIT() asm volatile("cp.async.commit_group;")
#define CP_WAIT(n)  asm volatile("cp.async.wait_group %0;" :: "n"(n))

__device__ __forceinline__ void mma_f16(float* c, uint32_t a0, uint32_t a1,
                                        uint32_t a2, uint32_t a3,
                                        uint32_t b0, uint32_t b1) {
    asm volatile(
        "mma.sync.aligned.m16n8k16.row.col.f32.f16.f16.f32 "
        "{%0,%1,%2,%3},{%4,%5,%6,%7},{%8,%9},{%0,%1,%2,%3};"
        : "+f"(c[0]), "+f"(c[1]), "+f"(c[2]), "+f"(c[3])
        : "r"(a0), "r"(a1), "r"(a2), "r"(a3), "r"(b0), "r"(b1));
}
__device__ __forceinline__ void ldm4(uint32_t* r, uint32_t addr) {
    asm volatile("ldmatrix.sync.aligned.m8n8.x4.shared.b16 {%0,%1,%2,%3}, [%4];"
        : "=r"(r[0]), "=r"(r[1]), "=r"(r[2]), "=r"(r[3]) : "r"(addr));
}

// ---------------------------------------------------------------------------
// Combined prep: x -> g_xpad (NCHW fp32) and g_xn (NHWC fp16), interiors only
// ---------------------------------------------------------------------------
__global__ __launch_bounds__(256) void prep_x(const float* __restrict__ x) {
    const int h = blockIdx.x, b = blockIdx.y;
    __half* outr = g_xn + (((size_t)b * XP + (h + 6))) * XP * CIN;
    __shared__ float sm[128 * 65];
    for (int half_i = 0; half_i < 2; half_i++) {
        const int ich = half_i * 128;
        for (int idx = threadIdx.x; idx < 128 * 64; idx += 256) {
            int icl = idx >> 6, w = idx & 63;
            sm[icl * 65 + w] = x[(((size_t)(b * CIN + ich + icl)) * HH + h) * WW + w];
        }
        __syncthreads();
        for (int idx = threadIdx.x; idx < 64 * 128; idx += 256) {
            int w = idx >> 7, icl = idx & 127;
            outr[(size_t)(w + 6) * CIN + ich + icl] = __float2half_rn(sm[icl * 65 + w]);
        }
        for (int idx = threadIdx.x; idx < 128 * 32; idx += 256) {
            int icl = idx >> 5, wp = (idx & 31) * 2;
            float2 v = make_float2(sm[icl * 65 + wp], sm[icl * 65 + wp + 1]);
            *(float2*)&g_xpad[((size_t)(b * CIN + ich + icl)) * XP * XP
                              + (h + 6) * XP + wp + 6] = v;
        }
        __syncthreads();
    }
}

// ---------------------------------------------------------------------------
// Fused weights as tiled GEMM over w1's native k' = ic*49+tap ordering.
// ---------------------------------------------------------------------------
__global__ __launch_bounds__(256) void fuse_w(const float* __restrict__ w1,
                                              const float* __restrict__ w2) {
    extern __shared__ float fsm[];
    float* w2s = fsm;
    float* sm  = fsm + OC2 * 128;
    const int tid = threadIdx.x;
    const int k0 = blockIdx.x * 128;

    for (int i = tid; i < OC2 * 128; i += 256) w2s[i] = w2[i];
    for (int i = tid; i < 128 * 128; i += 256) {
        int m = i >> 7, kcl = i & 127;
        sm[m * 130 + kcl] = w1[(size_t)m * KTOT + k0 + kcl];
    }
    __syncthreads();

    const int och = tid >> 6;
    const int kc0 = (tid & 63) * 2;
    const int oc0 = och * 12;
    const int ocn = (och < 3) ? 12 : 13;

    float accx[13], accy[13];
#pragma unroll
    for (int j = 0; j < 13; j++) { accx[j] = 0.f; accy[j] = 0.f; }

#pragma unroll 4
    for (int m = 0; m < 128; m++) {
        const float2 a = *(const float2*)&sm[m * 130 + kc0];
#pragma unroll
        for (int j = 0; j < 13; j++) {
            if (j < ocn) {
                const float wv = w2s[(oc0 + j) * 128 + m];
                accx[j] = fmaf(wv, a.x, accx[j]);
                accy[j] = fmaf(wv, a.y, accy[j]);
            }
        }
    }
#pragma unroll
    for (int j = 0; j < 13; j++) {
        if (j < ocn) {
#pragma unroll
            for (int e = 0; e < 2; e++) {
                const int kp = k0 + kc0 + e;
                const int ic = kp / 49, tap = kp - ic * 49;
                g_w12t[(size_t)(oc0 + j) * KTOT + tap * 256 + ic] =
                    __float2half_rn(e ? accy[j] : accx[j]);
            }
        }
    }
}

__global__ __launch_bounds__(128) void bias_fuse(const float* __restrict__ w2,
                                                 const float* __restrict__ b1,
                                                 const float* __restrict__ b2) {
    const int oc = blockIdx.x, tid = threadIdx.x;
    float v = w2[oc * 128 + tid] * b1[tid];
#pragma unroll
    for (int off = 16; off > 0; off >>= 1)
        v += __shfl_xor_sync(0xFFFFFFFFu, v, off);
    __shared__ float ws[4];
    if ((tid & 31) == 0) ws[tid >> 5] = v;
    __syncthreads();
    if (tid == 0) g_b12[oc] = ws[0] + ws[1] + ws[2] + ws[3] + b2[oc];
}

// ---------------------------------------------------------------------------
// fp16 mma.sync implicit-GEMM conv, K split across 2 CTAs (ic halves).
// CTA: M=128 px, N=64 oc, chunk K=128 (1 tap). Warp grid 4m x 2k:
// warp tile 32M x 64N x 64K -> A loaded once per CTA (no dup), B 4x.
// Crossbar reads/chunk: 96KB (was 128KB). k-halves summed in smem epilogue.
// ---------------------------------------------------------------------------
__global__ __launch_bounds__(256, 2) void conv_mma() {
    extern __shared__ __align__(16) char smem[];
    const uint32_t sbase = smem_u32(smem);
    const int tid = threadIdx.x, wid = tid >> 5, lane = tid & 31;
    const int gid = lane >> 2, tg = lane & 3;
    const int hr0 = blockIdx.x * 2, b = blockIdx.y, icq = blockIdx.z;
    const int wk = wid >> 2, wm = wid & 3;     // k-half, m-group
    const int mbase = wm * 32;
    const int icbase = icq * 128;
    const int kub = wk * 8;                    // 16B-unit base of this k-half

    float acc[2][8][4];
#pragma unroll
    for (int mt = 0; mt < 2; mt++)
#pragma unroll
        for (int nt = 0; nt < 8; nt++)
#pragma unroll
            for (int r = 0; r < 4; r++) acc[mt][nt][r] = 0.f;

    const int lhi16 = lane >> 4;
    const int bhi = (lane >> 3) & 1;
    int arow0[2];
    {
        const int rsel = ((lane >> 3) & 1) * 8 + (lane & 7);
#pragma unroll
        for (int mt = 0; mt < 2; mt++)
            arow0[mt] = (mbase >> 6) * 76 + (mbase & 63) + mt * 16 + rsel;
    }
    int brow[4];
#pragma unroll
    for (int ntp = 0; ntp < 4; ntp++)
        brow[ntp] = ntp * 16 + (lane >> 4) * 8 + (lane & 7);

    const __half* xb = g_xn + (size_t)b * XP * XP * CIN;

#define COPY_SLAB(u, slot) do {                                                 \
    const __half* _src = xb + ((size_t)(hr0 + 2 * (u)) * XP) * CIN + icbase;    \
    const uint32_t _dst = sbase + (slot) * SLAB_BYTES;                          \
    for (int _i = tid; _i < 2432; _i += 256) {                                  \
        int _row = _i >> 4, _j = _i & 15;                                       \
        int _pr = _row / 76, _col = _row - _pr * 76;                            \
        cp16(_dst + _row * 256 + ((_j ^ (_row & 7)) << 4),                      \
             _src + ((size_t)_pr * XP + _col) * CIN + _j * 8);                  \
    }                                                                           \
} while (0)

#define COPY_B(q, slot) do {                                                    \
    const __half* _bs = g_w12t + (q) * 256 + icbase;                            \
    const uint32_t _dst = sbase + BRING_OFF + (slot) * BTILE_BYTES;             \
    for (int _i = tid; _i < 1024; _i += 256) {                                  \
        int _oc = _i >> 4, _j = _i & 15;                                        \
        cp16(_dst + _oc * 256 + ((_j ^ (_oc & 7)) << 4),                        \
             _bs + (size_t)_oc * KTOT + _j * 8);                                \
    }                                                                           \
} while (0)

    COPY_SLAB(0, 0); COPY_B(0, 0); CP_COMMIT();

#pragma unroll 1
    for (int q = 0; q < NQ; q++) {
        CP_WAIT(0);
        __syncthreads();
        const int s = q / 7, v = q - s * 7;
        if (v == 0 && s + 1 < 7) COPY_SLAB(s + 1, (s + 1) & 1);
        if (q + 1 < NQ) COPY_B(q + 1, (q + 1) & 1);
        CP_COMMIT();

        const uint32_t Aaddr = sbase + (s & 1) * SLAB_BYTES;
        const uint32_t Baddr = sbase + BRING_OFF + (q & 1) * BTILE_BYTES;
        uint32_t Abase[2], Bbase[4];
        int amask[2], bmask[4];
#pragma unroll
        for (int mt = 0; mt < 2; mt++) {
            const int r = arow0[mt] + 2 * v;
            Abase[mt] = Aaddr + r * 256;
            amask[mt] = r & 7;
        }
#pragma unroll
        for (int ntp = 0; ntp < 4; ntp++) {
            Bbase[ntp] = Baddr + brow[ntp] * 256;
            bmask[ntp] = brow[ntp] & 7;
        }
#pragma unroll
        for (int ks = 0; ks < 4; ks++) {
            const int ua = kub + 2 * ks;
            uint32_t Ar[2][4], Br[4][4];
            ldm4(Ar[0], Abase[0] + (((ua + lhi16) ^ amask[0]) << 4));
            ldm4(Ar[1], Abase[1] + (((ua + lhi16) ^ amask[1]) << 4));
#pragma unroll
            for (int ntp = 0; ntp < 4; ntp++)
                ldm4(Br[ntp], Bbase[ntp] + (((ua + bhi) ^ bmask[ntp]) << 4));
#pragma unroll
            for (int mt = 0; mt < 2; mt++)
#pragma unroll
                for (int nt = 0; nt < 8; nt++)
                    mma_f16(acc[mt][nt], Ar[mt][0], Ar[mt][1], Ar[mt][2], Ar[mt][3],
                            Br[nt >> 1][(nt & 1) * 2], Br[nt >> 1][(nt & 1) * 2 + 1]);
        }
    }

    // ---- epilogue: sum k-halves in smem, then partial logits -> g_k2 -------
    __syncthreads();
    float* lg = (float*)smem;               // [128][66]
    if (wk == 0) {
#pragma unroll
        for (int mt = 0; mt < 2; mt++) {
            const int row0 = mbase + mt * 16 + gid;
#pragma unroll
            for (int nt = 0; nt < 8; nt++) {
                const int col = nt * 8 + tg * 2;
                *(float2*)&lg[row0 * 66 + col] =
                    make_float2(acc[mt][nt][0], acc[mt][nt][1]);
                *(float2*)&lg[(row0 + 8) * 66 + col] =
                    make_float2(acc[mt][nt][2], acc[mt][nt][3]);
            }
        }
    }
    __syncthreads();
    if (wk == 1) {
#pragma unroll
        for (int mt = 0; mt < 2; mt++) {
            const int row0 = mbase + mt * 16 + gid;
#pragma unroll
            for (int nt = 0; nt < 8; nt++) {
                const int col = nt * 8 + tg * 2;
                float2* p0 = (float2*)&lg[row0 * 66 + col];
                float2* p1 = (float2*)&lg[(row0 + 8) * 66 + col];
                float2 v0 = *p0, v1 = *p1;
                v0.x += acc[mt][nt][0]; v0.y += acc[mt][nt][1];
                v1.x += acc[mt][nt][2]; v1.y += acc[mt][nt][3];
                *p0 = v0; *p1 = v1;
            }
        }
    }
    __syncthreads();
    if (tid < 128) {
        const float* p = lg + tid * 66;
        float* dst = g_k2 + ((size_t)(icq * 4 + b) * OC2) * (HH * WW)
                     + (hr0 + (tid >> 6)) * WW + (tid & 63);
#pragma unroll
        for (int k = 0; k < OC2; k++)
            dst[(size_t)k * (HH * WW)] = p[k];
    }
#undef COPY_SLAB
#undef COPY_B
}

// ---------------------------------------------------------------------------
// Sum 2 ic-partials + fused bias, softmax over 49 channels -> g_attn
// ---------------------------------------------------------------------------
__global__ __launch_bounds__(128) void softmax_k() {
    const int b = blockIdx.y;
    const int px = blockIdx.x * 128 + threadIdx.x;
    __shared__ float bs[OC2];
    if (threadIdx.x < OC2) bs[threadIdx.x] = g_b12[threadIdx.x];
    __syncthreads();

    const float* p0 = g_k2 + ((size_t)(0 * 4 + b) * OC2) * (HH * WW) + px;
    const float* p1 = g_k2 + ((size_t)(1 * 4 + b) * OC2) * (HH * WW) + px;
    float v[OC2];
    float mx = -1e30f;
#pragma unroll
    for (int k = 0; k < OC2; k++) {
        v[k] = bs[k] + p0[(size_t)k * (HH * WW)] + p1[(size_t)k * (HH * WW)];
        mx = fmaxf(mx, v[k]);
    }
    float s = 0.f;
#pragma unroll
    for (int k = 0; k < OC2; k++) { v[k] = __expf(v[k] - mx); s += v[k]; }
    const float inv = 1.f / s;
#pragma unroll
    for (int k = 0; k < OC2; k++)
        g_attn[((size_t)(b * OC2 + k)) * (HH * WW) + px] = v[k] * inv;
}

// ---------------------------------------------------------------------------
// Gather: out[b,c,h,w] = sum_k attn[b,k,h,w] * xpad[b,c,h+2u,w+2v]
// 4 channels per group, separate buffers, cp16 fills, 3-buffer ring.
// ---------------------------------------------------------------------------
__global__ __launch_bounds__(256) void gather_kernel(float* __restrict__ out) {
    const int tile = blockIdx.x;                 // 8 h-tiles x 4 w-tiles
    const int h0 = (tile >> 2) * 8, w0 = (tile & 3) * 16;
    const int b = blockIdx.z;
    const int tid = threadIdx.x;
    const int sub = tid >> 7, stid = tid & 127;
    const int rr = stid >> 4, cc = stid & 15;
    const int h = h0 + rr, w = w0 + cc;
    const int c0 = blockIdx.y * 128 + sub * 64;

    __shared__ __align__(16) float xsm[3][2][4][20 * GSTRIDE];

    float attn[OC2];
#pragma unroll
    for (int k = 0; k < OC2; k++)
        attn[k] = g_attn[(((size_t)(b * OC2 + k)) * HH + h) * WW + w];

    uint32_t sb[3];
#pragma unroll
    for (int s = 0; s < 3; s++) sb[s] = smem_u32(&xsm[s][sub][0][0]);

    const float* plane0 = g_xpad + (((size_t)(b * CIN + c0)) * XP + h0) * XP + w0;

#define CPG(g, st) do {                                                         \
    for (int _ch = 0; _ch < 4; _ch++) {                                         \
        const float* _src = plane0 + (size_t)(4 * (g) + _ch) * XP * XP;         \
        const uint32_t _d = sb[st] + _ch * (20 * GSTRIDE * 4);                  \
        for (int _i = stid; _i < 140; _i += 128) {                              \
            int _r = _i / 7, _j = _i - _r * 7;                                  \
            cp16(_d + (_r * GSTRIDE + _j * 4) * 4, _src + _r * XP + _j * 4);    \
        }                                                                       \
    }                                                                           \
} while (0)

    CPG(0, 0); CP_COMMIT();
    CPG(1, 1); CP_COMMIT();

#pragma unroll 1
    for (int g = 0; g < 16; g++) {
        CP_WAIT(1);
        __syncthreads();
        if (g + 2 < 16) { CPG(g + 2, (g + 2) % 3); }
        CP_COMMIT();

        const float* xs = &xsm[g % 3][sub][0][0];
        float o0 = 0.f, o1 = 0.f, o2 = 0.f, o3 = 0.f;
#pragma unroll
        for (int u = 0; u < 7; u++)
#pragma unroll
            for (int v = 0; v < 7; v++) {
                const int idx = (rr + 2 * u) * GSTRIDE + cc + 2 * v;
                const float a = attn[u * 7 + v];
                o0 = fmaf(a, xs[idx], o0);
                o1 = fmaf(a, xs[idx + 960], o1);
                o2 = fmaf(a, xs[idx + 1920], o2);
                o3 = fmaf(a, xs[idx + 2880], o3);
            }
        float* dst = out + (((size_t)(b * CIN + c0 + 4 * g)) * HH + h) * WW + w;
        dst[0] = o0;
        dst[HH * WW] = o1;
        dst[2 * HH * WW] = o2;
        dst[3 * HH * WW] = o3;
    }
#undef CPG
}

// ---------------------------------------------------------------------------
extern "C" void kernel_launch(void* const* d_in, const int* in_sizes, int n_in,
                              void* d_out, int out_size)
{
    const float* x  = (const float*)d_in[0];
    const float* w1 = (const float*)d_in[1];
    const float* b1 = (const float*)d_in[2];
    const float* w2 = (const float*)d_in[3];
    const float* b2 = (const float*)d_in[4];
    float* out = (float*)d_out;

    cudaFuncSetAttribute(conv_mma, cudaFuncAttributeMaxDynamicSharedMemorySize,
                         SMEM_CONV);
    cudaFuncSetAttribute(fuse_w, cudaFuncAttributeMaxDynamicSharedMemorySize,
                         SMEM_FW);

    prep_x<<<dim3(HH, 4), 256>>>(x);
    fuse_w<<<98, 256, SMEM_FW>>>(w1, w2);
    bias_fuse<<<49, 128>>>(w2, b1, b2);
    conv_mma<<<dim3(32, 4, 2), 256, SMEM_CONV>>>();
    softmax_k<<<dim3(32, 4), 128>>>();
    gather_kernel<<<dim3(32, 2, 4), 256>>>(out);
}

// round 13
// speedup vs baseline: 1.2041x; 1.0459x over previous
#include <cuda_runtime.h>
#include <cuda_fp16.h>
#include <cstdint>

#define HH 64
#define WW 64
#define CIN 256
#define XP 76
#define OC2 49
#define KTOT 12544              // 49 taps * 256 ic
#define NQ 49                   // chunks per CTA: 1 tap x 128 ic (this CTA's half)
#define SLAB_BYTES (152 * 256)  // 2 padded rows x 76 cols x 128 ic fp16, swizzled
#define BTILE_BYTES (64 * 256)  // 64 oc x 128 ic fp16, swizzled
#define BRING_OFF (2 * SLAB_BYTES)
#define SMEM_CONV (BRING_OFF + 2 * BTILE_BYTES)   // 110592 -> 2 CTAs/SM
#define GSTRIDE 48
#define SMEM_FW (25088 + 128 * 130 * 4)

// Scratch (device globals: zero-initialized, allocation-free, graph-capturable)
__device__ float  g_xpad[4 * CIN * XP * XP];     // NCHW padded fp32 (gather)
__device__ __half g_xn[4 * XP * XP * CIN];       // NHWC padded fp16 (conv A)
__device__ __half g_w12t[64 * KTOT];             // fused W^T [oc64][tap*256+ic] fp16
__device__ float  g_b12[OC2];                    // fused bias
__device__ float  g_k2[2 * 4 * OC2 * HH * WW];   // partial logits [icq][b][oc][px]

// ---------------- helpers ----------------
__device__ __forceinline__ uint32_t smem_u32(const void* p) {
    uint32_t a;
    asm("{ .reg .u64 t; cvta.to.shared.u64 t, %1; cvt.u32.u64 %0, t; }" : "=r"(a) : "l"(p));
    return a;
}
__device__ __forceinline__ void cp16(uint32_t d, const void* s) {
    asm volatile("cp.async.cg.shared.global [%0], [%1], 16;" :: "r"(d), "l"(s));
}
#define CP_COMMIT() asm volatile("cp.async.commit_group;")
#define CP_WAIT(n)  asm volatile("cp.async.wait_group %0;" :: "n"(n))

__device__ __forceinline__ void mma_f16(float* c, uint32_t a0, uint32_t a1,
                                        uint32_t a2, uint32_t a3,
                                        uint32_t b0, uint32_t b1) {
    asm volatile(
        "mma.sync.aligned.m16n8k16.row.col.f32.f16.f16.f32 "
        "{%0,%1,%2,%3},{%4,%5,%6,%7},{%8,%9},{%0,%1,%2,%3};"
        : "+f"(c[0]), "+f"(c[1]), "+f"(c[2]), "+f"(c[3])
        : "r"(a0), "r"(a1), "r"(a2), "r"(a3), "r"(b0), "r"(b1));
}
__device__ __forceinline__ void ldm4(uint32_t* r, uint32_t addr) {
    asm volatile("ldmatrix.sync.aligned.m8n8.x4.shared.b16 {%0,%1,%2,%3}, [%4];"
        : "=r"(r[0]), "=r"(r[1]), "=r"(r[2]), "=r"(r[3]) : "r"(addr));
}

// ---------------------------------------------------------------------------
// Combined prep: x -> g_xpad (NCHW fp32) and g_xn (NHWC fp16), interiors only
// ---------------------------------------------------------------------------
__global__ __launch_bounds__(256) void prep_x(const float* __restrict__ x) {
    const int h = blockIdx.x, b = blockIdx.y;
    __half* outr = g_xn + (((size_t)b * XP + (h + 6))) * XP * CIN;
    __shared__ float sm[128 * 65];
    for (int half_i = 0; half_i < 2; half_i++) {
        const int ich = half_i * 128;
        for (int idx = threadIdx.x; idx < 128 * 64; idx += 256) {
            int icl = idx >> 6, w = idx & 63;
            sm[icl * 65 + w] = x[(((size_t)(b * CIN + ich + icl)) * HH + h) * WW + w];
        }
        __syncthreads();
        for (int idx = threadIdx.x; idx < 64 * 128; idx += 256) {
            int w = idx >> 7, icl = idx & 127;
            outr[(size_t)(w + 6) * CIN + ich + icl] = __float2half_rn(sm[icl * 65 + w]);
        }
        for (int idx = threadIdx.x; idx < 128 * 32; idx += 256) {
            int icl = idx >> 5, wp = (idx & 31) * 2;
            float2 v = make_float2(sm[icl * 65 + wp], sm[icl * 65 + wp + 1]);
            *(float2*)&g_xpad[((size_t)(b * CIN + ich + icl)) * XP * XP
                              + (h + 6) * XP + wp + 6] = v;
        }
        __syncthreads();
    }
}

// ---------------------------------------------------------------------------
// Fused weights as tiled GEMM (blocks 0..97) + fused bias (block 98).
// ---------------------------------------------------------------------------
__global__ __launch_bounds__(256) void fuse_w(const float* __restrict__ w1,
                                              const float* __restrict__ w2,
                                              const float* __restrict__ b1,
                                              const float* __restrict__ b2) {
    const int tid = threadIdx.x;
    if (blockIdx.x == 98) {                  // bias block
        if (tid < OC2) {
            float s = b2[tid];
#pragma unroll 4
            for (int m = 0; m < 128; m++)
                s = fmaf(w2[tid * 128 + m], b1[m], s);
            g_b12[tid] = s;
        }
        return;
    }
    extern __shared__ float fsm[];
    float* w2s = fsm;
    float* sm  = fsm + OC2 * 128;
    const int k0 = blockIdx.x * 128;

    for (int i = tid; i < OC2 * 128; i += 256) w2s[i] = w2[i];
    for (int i = tid; i < 128 * 128; i += 256) {
        int m = i >> 7, kcl = i & 127;
        sm[m * 130 + kcl] = w1[(size_t)m * KTOT + k0 + kcl];
    }
    __syncthreads();

    const int och = tid >> 6;
    const int kc0 = (tid & 63) * 2;
    const int oc0 = och * 12;
    const int ocn = (och < 3) ? 12 : 13;

    float accx[13], accy[13];
#pragma unroll
    for (int j = 0; j < 13; j++) { accx[j] = 0.f; accy[j] = 0.f; }

#pragma unroll 4
    for (int m = 0; m < 128; m++) {
        const float2 a = *(const float2*)&sm[m * 130 + kc0];
#pragma unroll
        for (int j = 0; j < 13; j++) {
            if (j < ocn) {
                const float wv = w2s[(oc0 + j) * 128 + m];
                accx[j] = fmaf(wv, a.x, accx[j]);
                accy[j] = fmaf(wv, a.y, accy[j]);
            }
        }
    }
#pragma unroll
    for (int j = 0; j < 13; j++) {
        if (j < ocn) {
#pragma unroll
            for (int e = 0; e < 2; e++) {
                const int kp = k0 + kc0 + e;
                const int ic = kp / 49, tap = kp - ic * 49;
                g_w12t[(size_t)(oc0 + j) * KTOT + tap * 256 + ic] =
                    __float2half_rn(e ? accy[j] : accx[j]);
            }
        }
    }
}

// ---------------------------------------------------------------------------
// fp16 mma.sync implicit-GEMM conv, K split across 2 CTAs (ic halves).
// Warp grid 4m x 2k; A loaded once per CTA, k-halves summed in smem epilogue.
// ---------------------------------------------------------------------------
__global__ __launch_bounds__(256, 2) void conv_mma() {
    extern __shared__ __align__(16) char smem[];
    const uint32_t sbase = smem_u32(smem);
    const int tid = threadIdx.x, wid = tid >> 5, lane = tid & 31;
    const int gid = lane >> 2, tg = lane & 3;
    const int hr0 = blockIdx.x * 2, b = blockIdx.y, icq = blockIdx.z;
    const int wk = wid >> 2, wm = wid & 3;
    const int mbase = wm * 32;
    const int icbase = icq * 128;
    const int kub = wk * 8;

    float acc[2][8][4];
#pragma unroll
    for (int mt = 0; mt < 2; mt++)
#pragma unroll
        for (int nt = 0; nt < 8; nt++)
#pragma unroll
            for (int r = 0; r < 4; r++) acc[mt][nt][r] = 0.f;

    const int lhi16 = lane >> 4;
    const int bhi = (lane >> 3) & 1;
    int arow0[2];
    {
        const int rsel = ((lane >> 3) & 1) * 8 + (lane & 7);
#pragma unroll
        for (int mt = 0; mt < 2; mt++)
            arow0[mt] = (mbase >> 6) * 76 + (mbase & 63) + mt * 16 + rsel;
    }
    int brow[4];
#pragma unroll
    for (int ntp = 0; ntp < 4; ntp++)
        brow[ntp] = ntp * 16 + (lane >> 4) * 8 + (lane & 7);

    const __half* xb = g_xn + (size_t)b * XP * XP * CIN;

#define COPY_SLAB(u, slot) do {                                                 \
    const __half* _src = xb + ((size_t)(hr0 + 2 * (u)) * XP) * CIN + icbase;    \
    const uint32_t _dst = sbase + (slot) * SLAB_BYTES;                          \
    for (int _i = tid; _i < 2432; _i += 256) {                                  \
        int _row = _i >> 4, _j = _i & 15;                                       \
        int _pr = _row / 76, _col = _row - _pr * 76;                            \
        cp16(_dst + _row * 256 + ((_j ^ (_row & 7)) << 4),                      \
             _src + ((size_t)_pr * XP + _col) * CIN + _j * 8);                  \
    }                                                                           \
} while (0)

#define COPY_B(q, slot) do {                                                    \
    const __half* _bs = g_w12t + (q) * 256 + icbase;                            \
    const uint32_t _dst = sbase + BRING_OFF + (slot) * BTILE_BYTES;             \
    for (int _i = tid; _i < 1024; _i += 256) {                                  \
        int _oc = _i >> 4, _j = _i & 15;                                        \
        cp16(_dst + _oc * 256 + ((_j ^ (_oc & 7)) << 4),                        \
             _bs + (size_t)_oc * KTOT + _j * 8);                                \
    }                                                                           \
} while (0)

    COPY_SLAB(0, 0); COPY_B(0, 0); CP_COMMIT();

#pragma unroll 1
    for (int q = 0; q < NQ; q++) {
        CP_WAIT(0);
        __syncthreads();
        const int s = q / 7, v = q - s * 7;
        if (v == 0 && s + 1 < 7) COPY_SLAB(s + 1, (s + 1) & 1);
        if (q + 1 < NQ) COPY_B(q + 1, (q + 1) & 1);
        CP_COMMIT();

        const uint32_t Aaddr = sbase + (s & 1) * SLAB_BYTES;
        const uint32_t Baddr = sbase + BRING_OFF + (q & 1) * BTILE_BYTES;
        uint32_t Abase[2], Bbase[4];
        int amask[2], bmask[4];
#pragma unroll
        for (int mt = 0; mt < 2; mt++) {
            const int r = arow0[mt] + 2 * v;
            Abase[mt] = Aaddr + r * 256;
            amask[mt] = r & 7;
        }
#pragma unroll
        for (int ntp = 0; ntp < 4; ntp++) {
            Bbase[ntp] = Baddr + brow[ntp] * 256;
            bmask[ntp] = brow[ntp] & 7;
        }
#pragma unroll
        for (int ks = 0; ks < 4; ks++) {
            const int ua = kub + 2 * ks;
            uint32_t Ar[2][4], Br[4][4];
            ldm4(Ar[0], Abase[0] + (((ua + lhi16) ^ amask[0]) << 4));
            ldm4(Ar[1], Abase[1] + (((ua + lhi16) ^ amask[1]) << 4));
#pragma unroll
            for (int ntp = 0; ntp < 4; ntp++)
                ldm4(Br[ntp], Bbase[ntp] + (((ua + bhi) ^ bmask[ntp]) << 4));
#pragma unroll
            for (int mt = 0; mt < 2; mt++)
#pragma unroll
                for (int nt = 0; nt < 8; nt++)
                    mma_f16(acc[mt][nt], Ar[mt][0], Ar[mt][1], Ar[mt][2], Ar[mt][3],
                            Br[nt >> 1][(nt & 1) * 2], Br[nt >> 1][(nt & 1) * 2 + 1]);
        }
    }

    // ---- epilogue: sum k-halves in smem, then partial logits -> g_k2 -------
    __syncthreads();
    float* lg = (float*)smem;               // [128][66]
    if (wk == 0) {
#pragma unroll
        for (int mt = 0; mt < 2; mt++) {
            const int row0 = mbase + mt * 16 + gid;
#pragma unroll
            for (int nt = 0; nt < 8; nt++) {
                const int col = nt * 8 + tg * 2;
                *(float2*)&lg[row0 * 66 + col] =
                    make_float2(acc[mt][nt][0], acc[mt][nt][1]);
                *(float2*)&lg[(row0 + 8) * 66 + col] =
                    make_float2(acc[mt][nt][2], acc[mt][nt][3]);
            }
        }
    }
    __syncthreads();
    if (wk == 1) {
#pragma unroll
        for (int mt = 0; mt < 2; mt++) {
            const int row0 = mbase + mt * 16 + gid;
#pragma unroll
            for (int nt = 0; nt < 8; nt++) {
                const int col = nt * 8 + tg * 2;
                float2* p0 = (float2*)&lg[row0 * 66 + col];
                float2* p1 = (float2*)&lg[(row0 + 8) * 66 + col];
                float2 v0 = *p0, v1 = *p1;
                v0.x += acc[mt][nt][0]; v0.y += acc[mt][nt][1];
                v1.x += acc[mt][nt][2]; v1.y += acc[mt][nt][3];
                *p0 = v0; *p1 = v1;
            }
        }
    }
    __syncthreads();
    if (tid < 128) {
        const float* p = lg + tid * 66;
        float* dst = g_k2 + ((size_t)(icq * 4 + b) * OC2) * (HH * WW)
                     + (hr0 + (tid >> 6)) * WW + (tid & 63);
#pragma unroll
        for (int k = 0; k < OC2; k++)
            dst[(size_t)k * (HH * WW)] = p[k];
    }
#undef COPY_SLAB
#undef COPY_B
}

// ---------------------------------------------------------------------------
// Gather with fused softmax: attn computed from g_k2 partials + bias per px.
// 4 channels per group, cp16 fills, 3-buffer ring.
// ---------------------------------------------------------------------------
__global__ __launch_bounds__(256) void gather_kernel(float* __restrict__ out) {
    const int tile = blockIdx.x;                 // 8 h-tiles x 4 w-tiles
    const int h0 = (tile >> 2) * 8, w0 = (tile & 3) * 16;
    const int b = blockIdx.z;
    const int tid = threadIdx.x;
    const int sub = tid >> 7, stid = tid & 127;
    const int rr = stid >> 4, cc = stid & 15;
    const int h = h0 + rr, w = w0 + cc;
    const int c0 = blockIdx.y * 128 + sub * 64;

    __shared__ __align__(16) float xsm[3][2][4][20 * GSTRIDE];

    // ---- fused softmax: attn[k] from the two ic-partials + bias ----
    float attn[OC2];
    {
        const int pxoff = h * WW + w;
        const float* p0 = g_k2 + ((size_t)(0 * 4 + b) * OC2) * (HH * WW) + pxoff;
        const float* p1 = g_k2 + ((size_t)(1 * 4 + b) * OC2) * (HH * WW) + pxoff;
        float mx = -1e30f;
#pragma unroll
        for (int k = 0; k < OC2; k++) {
            attn[k] = p0[(size_t)k * (HH * WW)] + p1[(size_t)k * (HH * WW)]
                      + __ldg(&g_b12[k]);
            mx = fmaxf(mx, attn[k]);
        }
        float s = 0.f;
#pragma unroll
        for (int k = 0; k < OC2; k++) { attn[k] = __expf(attn[k] - mx); s += attn[k]; }
        const float inv = 1.f / s;
#pragma unroll
        for (int k = 0; k < OC2; k++) attn[k] *= inv;
    }

    uint32_t sb[3];
#pragma unroll
    for (int s = 0; s < 3; s++) sb[s] = smem_u32(&xsm[s][sub][0][0]);

    const float* plane0 = g_xpad + (((size_t)(b * CIN + c0)) * XP + h0) * XP + w0;

#define CPG(g, st) do {                                                         \
    for (int _ch = 0; _ch < 4; _ch++) {                                         \
        const float* _src = plane0 + (size_t)(4 * (g) + _ch) * XP * XP;         \
        const uint32_t _d = sb[st] + _ch * (20 * GSTRIDE * 4);                  \
        for (int _i = stid; _i < 140; _i += 128) {                              \
            int _r = _i / 7, _j = _i - _r * 7;                                  \
            cp16(_d + (_r * GSTRIDE + _j * 4) * 4, _src + _r * XP + _j * 4);    \
        }                                                                       \
    }                                                                           \
} while (0)

    CPG(0, 0); CP_COMMIT();
    CPG(1, 1); CP_COMMIT();

#pragma unroll 1
    for (int g = 0; g < 16; g++) {
        CP_WAIT(1);
        __syncthreads();
        if (g + 2 < 16) { CPG(g + 2, (g + 2) % 3); }
        CP_COMMIT();

        const float* xs = &xsm[g % 3][sub][0][0];
        float o0 = 0.f, o1 = 0.f, o2 = 0.f, o3 = 0.f;
#pragma unroll
        for (int u = 0; u < 7; u++)
#pragma unroll
            for (int v = 0; v < 7; v++) {
                const int idx = (rr + 2 * u) * GSTRIDE + cc + 2 * v;
                const float a = attn[u * 7 + v];
                o0 = fmaf(a, xs[idx], o0);
                o1 = fmaf(a, xs[idx + 960], o1);
                o2 = fmaf(a, xs[idx + 1920], o2);
                o3 = fmaf(a, xs[idx + 2880], o3);
            }
        float* dst = out + (((size_t)(b * CIN + c0 + 4 * g)) * HH + h) * WW + w;
        dst[0] = o0;
        dst[HH * WW] = o1;
        dst[2 * HH * WW] = o2;
        dst[3 * HH * WW] = o3;
    }
#undef CPG
}

// ---------------------------------------------------------------------------
extern "C" void kernel_launch(void* const* d_in, const int* in_sizes, int n_in,
                              void* d_out, int out_size)
{
    const float* x  = (const float*)d_in[0];
    const float* w1 = (const float*)d_in[1];
    const float* b1 = (const float*)d_in[2];
    const float* w2 = (const float*)d_in[3];
    const float* b2 = (const float*)d_in[4];
    float* out = (float*)d_out;

    cudaFuncSetAttribute(conv_mma, cudaFuncAttributeMaxDynamicSharedMemorySize,
                         SMEM_CONV);
    cudaFuncSetAttribute(fuse_w, cudaFuncAttributeMaxDynamicSharedMemorySize,
                         SMEM_FW);

    prep_x<<<dim3(HH, 4), 256>>>(x);
    fuse_w<<<99, 256, SMEM_FW>>>(w1, w2, b1, b2);
    conv_mma<<<dim3(32, 4, 2), 256, SMEM_CONV>>>();
    gather_kernel<<<dim3(32, 2, 4), 256>>>(out);
}

// round 14
// speedup vs baseline: 1.2390x; 1.0290x over previous
#include <cuda_runtime.h>
#include <cuda_fp16.h>
#include <cstdint>

#define HH 64
#define WW 64
#define CIN 256
#define XP 76
#define OC2 49
#define KTOT 12544              // 49 taps * 256 ic
#define NQ 49                   // chunks per CTA: 1 tap x 128 ic (this CTA's half)
#define SLAB_BYTES (152 * 256)  // 2 padded rows x 76 cols x 128 ic fp16, swizzled
#define BTILE_BYTES (64 * 256)  // 64 oc x 128 ic fp16, swizzled
#define BRING_OFF (2 * SLAB_BYTES)
#define SMEM_CONV (BRING_OFF + 2 * BTILE_BYTES)   // 110592 -> 2 CTAs/SM
#define GS4 28                  // gather smem row stride in float4 sites
#define SMEM_FW (25088 + 128 * 130 * 4)

// Scratch (device globals: zero-initialized, allocation-free, graph-capturable)
__device__ float4 g_xi[4 * 64 * XP * XP];        // padded x, 4-ch interleaved (gather)
__device__ __half g_xn[4 * XP * XP * CIN];       // NHWC padded fp16 (conv A)
__device__ __half g_w12t[64 * KTOT];             // fused W^T [oc64][tap*256+ic] fp16
__device__ float  g_b12[OC2];                    // fused bias
__device__ float  g_k2[2 * 4 * OC2 * HH * WW];   // partial logits [icq][b][oc][px]

// ---------------- helpers ----------------
__device__ __forceinline__ uint32_t smem_u32(const void* p) {
    uint32_t a;
    asm("{ .reg .u64 t; cvta.to.shared.u64 t, %1; cvt.u32.u64 %0, t; }" : "=r"(a) : "l"(p));
    return a;
}
__device__ __forceinline__ void cp16(uint32_t d, const void* s) {
    asm volatile("cp.async.cg.shared.global [%0], [%1], 16;" :: "r"(d), "l"(s));
}
#define CP_COMMIT() asm volatile("cp.async.commit_group;")
#define CP_WAIT(n)  asm volatile("cp.async.wait_group %0;" :: "n"(n))

__device__ __forceinline__ void mma_f16(float* c, uint32_t a0, uint32_t a1,
                                        uint32_t a2, uint32_t a3,
                                        uint32_t b0, uint32_t b1) {
    asm volatile(
        "mma.sync.aligned.m16n8k16.row.col.f32.f16.f16.f32 "
        "{%0,%1,%2,%3},{%4,%5,%6,%7},{%8,%9},{%0,%1,%2,%3};"
        : "+f"(c[0]), "+f"(c[1]), "+f"(c[2]), "+f"(c[3])
        : "r"(a0), "r"(a1), "r"(a2), "r"(a3), "r"(b0), "r"(b1));
}
__device__ __forceinline__ void ldm4(uint32_t* r, uint32_t addr) {
    asm volatile("ldmatrix.sync.aligned.m8n8.x4.shared.b16 {%0,%1,%2,%3}, [%4];"
        : "=r"(r[0]), "=r"(r[1]), "=r"(r[2]), "=r"(r[3]) : "r"(addr));
}

// ---------------------------------------------------------------------------
// Combined prep: x -> g_xi (4-ch interleaved fp32) and g_xn (NHWC fp16)
// ---------------------------------------------------------------------------
__global__ __launch_bounds__(256) void prep_x(const float* __restrict__ x) {
    const int h = blockIdx.x, b = blockIdx.y;
    __half* outr = g_xn + (((size_t)b * XP + (h + 6))) * XP * CIN;
    __shared__ float sm[128 * 65];
    for (int half_i = 0; half_i < 2; half_i++) {
        const int ich = half_i * 128;
        for (int idx = threadIdx.x; idx < 128 * 64; idx += 256) {
            int icl = idx >> 6, w = idx & 63;
            sm[icl * 65 + w] = x[(((size_t)(b * CIN + ich + icl)) * HH + h) * WW + w];
        }
        __syncthreads();
        // NHWC fp16 (conv A)
        for (int idx = threadIdx.x; idx < 64 * 128; idx += 256) {
            int w = idx >> 7, icl = idx & 127;
            outr[(size_t)(w + 6) * CIN + ich + icl] = __float2half_rn(sm[icl * 65 + w]);
        }
        // 4-ch interleaved fp32 (gather): cg local 0..31, ch = cg*4+e
        for (int idx = threadIdx.x; idx < 32 * 64; idx += 256) {
            int cgl = idx >> 6, w = idx & 63;
            float4 v = make_float4(sm[(4 * cgl + 0) * 65 + w],
                                   sm[(4 * cgl + 1) * 65 + w],
                                   sm[(4 * cgl + 2) * 65 + w],
                                   sm[(4 * cgl + 3) * 65 + w]);
            g_xi[(((size_t)(b * 64 + half_i * 32 + cgl)) * XP + (h + 6)) * XP
                 + (w + 6)] = v;
        }
        __syncthreads();
    }
}

// ---------------------------------------------------------------------------
// Fused weights as tiled GEMM (blocks 0..97) + fused bias (block 98).
// ---------------------------------------------------------------------------
__global__ __launch_bounds__(256) void fuse_w(const float* __restrict__ w1,
                                              const float* __restrict__ w2,
                                              const float* __restrict__ b1,
                                              const float* __restrict__ b2) {
    const int tid = threadIdx.x;
    if (blockIdx.x == 98) {                  // bias block
        if (tid < OC2) {
            float s = b2[tid];
#pragma unroll 4
            for (int m = 0; m < 128; m++)
                s = fmaf(w2[tid * 128 + m], b1[m], s);
            g_b12[tid] = s;
        }
        return;
    }
    extern __shared__ float fsm[];
    float* w2s = fsm;
    float* sm  = fsm + OC2 * 128;
    const int k0 = blockIdx.x * 128;

    for (int i = tid; i < OC2 * 128; i += 256) w2s[i] = w2[i];
    for (int i = tid; i < 128 * 128; i += 256) {
        int m = i >> 7, kcl = i & 127;
        sm[m * 130 + kcl] = w1[(size_t)m * KTOT + k0 + kcl];
    }
    __syncthreads();

    const int och = tid >> 6;
    const int kc0 = (tid & 63) * 2;
    const int oc0 = och * 12;
    const int ocn = (och < 3) ? 12 : 13;

    float accx[13], accy[13];
#pragma unroll
    for (int j = 0; j < 13; j++) { accx[j] = 0.f; accy[j] = 0.f; }

#pragma unroll 4
    for (int m = 0; m < 128; m++) {
        const float2 a = *(const float2*)&sm[m * 130 + kc0];
#pragma unroll
        for (int j = 0; j < 13; j++) {
            if (j < ocn) {
                const float wv = w2s[(oc0 + j) * 128 + m];
                accx[j] = fmaf(wv, a.x, accx[j]);
                accy[j] = fmaf(wv, a.y, accy[j]);
            }
        }
    }
#pragma unroll
    for (int j = 0; j < 13; j++) {
        if (j < ocn) {
#pragma unroll
            for (int e = 0; e < 2; e++) {
                const int kp = k0 + kc0 + e;
                const int ic = kp / 49, tap = kp - ic * 49;
                g_w12t[(size_t)(oc0 + j) * KTOT + tap * 256 + ic] =
                    __float2half_rn(e ? accy[j] : accx[j]);
            }
        }
    }
}

// ---------------------------------------------------------------------------
// fp16 mma.sync implicit-GEMM conv, K split across 2 CTAs (ic halves).
// Warp grid 4m x 2k; A loaded once per CTA, k-halves summed in smem epilogue.
// ---------------------------------------------------------------------------
__global__ __launch_bounds__(256, 2) void conv_mma() {
    extern __shared__ __align__(16) char smem[];
    const uint32_t sbase = smem_u32(smem);
    const int tid = threadIdx.x, wid = tid >> 5, lane = tid & 31;
    const int gid = lane >> 2, tg = lane & 3;
    const int hr0 = blockIdx.x * 2, b = blockIdx.y, icq = blockIdx.z;
    const int wk = wid >> 2, wm = wid & 3;
    const int mbase = wm * 32;
    const int icbase = icq * 128;
    const int kub = wk * 8;

    float acc[2][8][4];
#pragma unroll
    for (int mt = 0; mt < 2; mt++)
#pragma unroll
        for (int nt = 0; nt < 8; nt++)
#pragma unroll
            for (int r = 0; r < 4; r++) acc[mt][nt][r] = 0.f;

    const int lhi16 = lane >> 4;
    const int bhi = (lane >> 3) & 1;
    int arow0[2];
    {
        const int rsel = ((lane >> 3) & 1) * 8 + (lane & 7);
#pragma unroll
        for (int mt = 0; mt < 2; mt++)
            arow0[mt] = (mbase >> 6) * 76 + (mbase & 63) + mt * 16 + rsel;
    }
    int brow[4];
#pragma unroll
    for (int ntp = 0; ntp < 4; ntp++)
        brow[ntp] = ntp * 16 + (lane >> 4) * 8 + (lane & 7);

    const __half* xb = g_xn + (size_t)b * XP * XP * CIN;

#define COPY_SLAB(u, slot) do {                                                 \
    const __half* _src = xb + ((size_t)(hr0 + 2 * (u)) * XP) * CIN + icbase;    \
    const uint32_t _dst = sbase + (slot) * SLAB_BYTES;                          \
    for (int _i = tid; _i < 2432; _i += 256) {                                  \
        int _row = _i >> 4, _j = _i & 15;                                       \
        int _pr = _row / 76, _col = _row - _pr * 76;                            \
        cp16(_dst + _row * 256 + ((_j ^ (_row & 7)) << 4),                      \
             _src + ((size_t)_pr * XP + _col) * CIN + _j * 8);                  \
    }                                                                           \
} while (0)

#define COPY_B(q, slot) do {                                                    \
    const __half* _bs = g_w12t + (q) * 256 + icbase;                            \
    const uint32_t _dst = sbase + BRING_OFF + (slot) * BTILE_BYTES;             \
    for (int _i = tid; _i < 1024; _i += 256) {                                  \
        int _oc = _i >> 4, _j = _i & 15;                                        \
        cp16(_dst + _oc * 256 + ((_j ^ (_oc & 7)) << 4),                        \
             _bs + (size_t)_oc * KTOT + _j * 8);                                \
    }                                                                           \
} while (0)

    COPY_SLAB(0, 0); COPY_B(0, 0); CP_COMMIT();

#pragma unroll 1
    for (int q = 0; q < NQ; q++) {
        CP_WAIT(0);
        __syncthreads();
        const int s = q / 7, v = q - s * 7;
        if (v == 0 && s + 1 < 7) COPY_SLAB(s + 1, (s + 1) & 1);
        if (q + 1 < NQ) COPY_B(q + 1, (q + 1) & 1);
        CP_COMMIT();

        const uint32_t Aaddr = sbase + (s & 1) * SLAB_BYTES;
        const uint32_t Baddr = sbase + BRING_OFF + (q & 1) * BTILE_BYTES;
        uint32_t Abase[2], Bbase[4];
        int amask[2], bmask[4];
#pragma unroll
        for (int mt = 0; mt < 2; mt++) {
            const int r = arow0[mt] + 2 * v;
            Abase[mt] = Aaddr + r * 256;
            amask[mt] = r & 7;
        }
#pragma unroll
        for (int ntp = 0; ntp < 4; ntp++) {
            Bbase[ntp] = Baddr + brow[ntp] * 256;
            bmask[ntp] = brow[ntp] & 7;
        }
#pragma unroll
        for (int ks = 0; ks < 4; ks++) {
            const int ua = kub + 2 * ks;
            uint32_t Ar[2][4], Br[4][4];
            ldm4(Ar[0], Abase[0] + (((ua + lhi16) ^ amask[0]) << 4));
            ldm4(Ar[1], Abase[1] + (((ua + lhi16) ^ amask[1]) << 4));
#pragma unroll
            for (int ntp = 0; ntp < 4; ntp++)
                ldm4(Br[ntp], Bbase[ntp] + (((ua + bhi) ^ bmask[ntp]) << 4));
#pragma unroll
            for (int mt = 0; mt < 2; mt++)
#pragma unroll
                for (int nt = 0; nt < 8; nt++)
                    mma_f16(acc[mt][nt], Ar[mt][0], Ar[mt][1], Ar[mt][2], Ar[mt][3],
                            Br[nt >> 1][(nt & 1) * 2], Br[nt >> 1][(nt & 1) * 2 + 1]);
        }
    }

    // ---- epilogue: sum k-halves in smem, then partial logits -> g_k2 -------
    __syncthreads();
    float* lg = (float*)smem;               // [128][66]
    if (wk == 0) {
#pragma unroll
        for (int mt = 0; mt < 2; mt++) {
            const int row0 = mbase + mt * 16 + gid;
#pragma unroll
            for (int nt = 0; nt < 8; nt++) {
                const int col = nt * 8 + tg * 2;
                *(float2*)&lg[row0 * 66 + col] =
                    make_float2(acc[mt][nt][0], acc[mt][nt][1]);
                *(float2*)&lg[(row0 + 8) * 66 + col] =
                    make_float2(acc[mt][nt][2], acc[mt][nt][3]);
            }
        }
    }
    __syncthreads();
    if (wk == 1) {
#pragma unroll
        for (int mt = 0; mt < 2; mt++) {
            const int row0 = mbase + mt * 16 + gid;
#pragma unroll
            for (int nt = 0; nt < 8; nt++) {
                const int col = nt * 8 + tg * 2;
                float2* p0 = (float2*)&lg[row0 * 66 + col];
                float2* p1 = (float2*)&lg[(row0 + 8) * 66 + col];
                float2 v0 = *p0, v1 = *p1;
                v0.x += acc[mt][nt][0]; v0.y += acc[mt][nt][1];
                v1.x += acc[mt][nt][2]; v1.y += acc[mt][nt][3];
                *p0 = v0; *p1 = v1;
            }
        }
    }
    __syncthreads();
    if (tid < 128) {
        const float* p = lg + tid * 66;
        float* dst = g_k2 + ((size_t)(icq * 4 + b) * OC2) * (HH * WW)
                     + (hr0 + (tid >> 6)) * WW + (tid & 63);
#pragma unroll
        for (int k = 0; k < OC2; k++)
            dst[(size_t)k * (HH * WW)] = p[k];
    }
#undef COPY_SLAB
#undef COPY_B
}

// ---------------------------------------------------------------------------
// Gather with fused softmax; x read from 4-ch-interleaved g_xi.
// Inner loop: one LDS.128 per tap (4 channels at once).
// ---------------------------------------------------------------------------
__global__ __launch_bounds__(256) void gather_kernel(float* __restrict__ out) {
    const int tile = blockIdx.x;                 // 8 h-tiles x 4 w-tiles
    const int h0 = (tile >> 2) * 8, w0 = (tile & 3) * 16;
    const int b = blockIdx.z;
    const int tid = threadIdx.x;
    const int sub = tid >> 7, stid = tid & 127;
    const int rr = stid >> 4, cc = stid & 15;
    const int h = h0 + rr, w = w0 + cc;
    const int cg0 = blockIdx.y * 32 + sub * 16;  // float4 channel-group base

    __shared__ __align__(16) float4 xsm[3][2][20 * GS4];

    // ---- fused softmax: attn[k] from the two ic-partials + bias ----
    float attn[OC2];
    {
        const int pxoff = h * WW + w;
        const float* p0 = g_k2 + ((size_t)(0 * 4 + b) * OC2) * (HH * WW) + pxoff;
        const float* p1 = g_k2 + ((size_t)(1 * 4 + b) * OC2) * (HH * WW) + pxoff;
        float mx = -1e30f;
#pragma unroll
        for (int k = 0; k < OC2; k++) {
            attn[k] = p0[(size_t)k * (HH * WW)] + p1[(size_t)k * (HH * WW)]
                      + __ldg(&g_b12[k]);
            mx = fmaxf(mx, attn[k]);
        }
        float s = 0.f;
#pragma unroll
        for (int k = 0; k < OC2; k++) { attn[k] = __expf(attn[k] - mx); s += attn[k]; }
        const float inv = 1.f / s;
#pragma unroll
        for (int k = 0; k < OC2; k++) attn[k] *= inv;
    }

    uint32_t sb[3];
#pragma unroll
    for (int s = 0; s < 3; s++) sb[s] = smem_u32(&xsm[s][sub][0]);

    const float4* plane0 = g_xi + (((size_t)(b * 64 + cg0)) * XP + h0) * XP + w0;

#define CPG(g, st) do {                                                         \
    const float4* _src = plane0 + (size_t)(g) * XP * XP;                        \
    for (int _i = stid; _i < 560; _i += 128) {                                  \
        int _r = _i / GS4, _c = _i - _r * GS4;                                  \
        cp16(sb[st] + _i * 16, _src + _r * XP + _c);                            \
    }                                                                           \
} while (0)

    CPG(0, 0); CP_COMMIT();
    CPG(1, 1); CP_COMMIT();

#pragma unroll 1
    for (int g = 0; g < 16; g++) {
        CP_WAIT(1);
        __syncthreads();
        if (g + 2 < 16) { CPG(g + 2, (g + 2) % 3); }
        CP_COMMIT();

        const float4* xs = &xsm[g % 3][sub][0];
        float o0 = 0.f, o1 = 0.f, o2 = 0.f, o3 = 0.f;
#pragma unroll
        for (int u = 0; u < 7; u++)
#pragma unroll
            for (int v = 0; v < 7; v++) {
                const float4 xv = xs[(rr + 2 * u) * GS4 + cc + 2 * v];
                const float a = attn[u * 7 + v];
                o0 = fmaf(a, xv.x, o0);
                o1 = fmaf(a, xv.y, o1);
                o2 = fmaf(a, xv.z, o2);
                o3 = fmaf(a, xv.w, o3);
            }
        float* dst = out + (((size_t)(b * CIN + (cg0 + g) * 4)) * HH + h) * WW + w;
        dst[0] = o0;
        dst[HH * WW] = o1;
        dst[2 * HH * WW] = o2;
        dst[3 * HH * WW] = o3;
    }
#undef CPG
}

// ---------------------------------------------------------------------------
extern "C" void kernel_launch(void* const* d_in, const int* in_sizes, int n_in,
                              void* d_out, int out_size)
{
    const float* x  = (const float*)d_in[0];
    const float* w1 = (const float*)d_in[1];
    const float* b1 = (const float*)d_in[2];
    const float* w2 = (const float*)d_in[3];
    const float* b2 = (const float*)d_in[4];
    float* out = (float*)d_out;

    cudaFuncSetAttribute(conv_mma, cudaFuncAttributeMaxDynamicSharedMemorySize,
                         SMEM_CONV);
    cudaFuncSetAttribute(fuse_w, cudaFuncAttributeMaxDynamicSharedMemorySize,
                         SMEM_FW);

    prep_x<<<dim3(HH, 4), 256>>>(x);
    fuse_w<<<99, 256, SMEM_FW>>>(w1, w2, b1, b2);
    conv_mma<<<dim3(32, 4, 2), 256, SMEM_CONV>>>();
    gather_kernel<<<dim3(32, 2, 4), 256>>>(out);
}